// round 11
// baseline (speedup 1.0000x reference)
#include <cuda_runtime.h>
#include <math.h>

#define DD   1024
#define NH   16
#define HDIM 64
#define FF   2048
#define BB   8
#define SS   1027
#define SP   1056
#define EPSL 1e-5f
#define NC   32
#define NB   128            // persistent-kernel block count (<= 148 SMs)

typedef unsigned long long ull;

__device__ __forceinline__ ull pack2same(float v) {
    unsigned u = __float_as_uint(v);
    return ((ull)u << 32) | u;
}
#define FMA2(d, a, b) asm("fma.rn.f32x2 %0, %1, %2, %0;" : "+l"(d) : "l"(a), "l"(b))
#define ADD2(d, a, b) asm("add.rn.f32x2 %0, %1, %2;" : "=l"(d) : "l"(a), "l"(b))

__device__ float g_scores[(size_t)BB * NH * SP];
__device__ float g_minv[BB * NH * 2];
__device__ float g_qhat[NH * DD];
__device__ float g_qb[NH];
__device__ float g_ctxp[(size_t)BB * NC * NH * DD];
__device__ float g_ctx[(size_t)BB * NH * DD];
__device__ float g_oattn[BB * DD];
__device__ float g_ores[BB * DD];
__device__ float g_h1[BB * DD];
__device__ float g_f[BB * FF];
__device__ float g_f2[BB * DD];

// ---------- hand-rolled grid barrier (all NB blocks co-resident) --------------
__device__ unsigned g_count;
__device__ volatile unsigned g_gen;

__device__ __forceinline__ void grid_sync() {
    __threadfence();
    __syncthreads();
    if (threadIdx.x == 0) {
        unsigned my = g_gen;
        if (atomicAdd(&g_count, 1u) == NB - 1) {
            g_count = 0;
            __threadfence();
            g_gen = my + 1;
        } else {
            while (g_gen == my) __nanosleep(64);
        }
    }
    __syncthreads();
    __threadfence();
}

// ---------- position fetch helper ---------------------------------------------
__device__ __forceinline__ void fetch_pos(
    int s, int lx, int ly, int b, int lane,
    const float* __restrict__ x, const float* __restrict__ y,
    const float* __restrict__ cls, const float* __restrict__ sep,
    const float4* __restrict__ pxs4, const float4* __restrict__ pys4,
    float4 v[8]) {
    if (s == 0) {
        const float4* c4 = (const float4*)cls;
        #pragma unroll
        for (int k = 0; k < 8; k++) v[k] = __ldg(&c4[lane + 32 * k]);
    } else if (s <= lx) {
        const float4* xr = (const float4*)(x + ((size_t)b * 512 + (s - 1)) * DD);
        #pragma unroll
        for (int k = 0; k < 8; k++) {
            float4 a = __ldg(&xr[lane + 32 * k]), p = pxs4[lane + 32 * k];
            v[k].x = a.x + p.x; v[k].y = a.y + p.y; v[k].z = a.z + p.z; v[k].w = a.w + p.w;
        }
    } else if (s == lx + 1 || s == lx + ly + 2) {
        const float4* s4 = (const float4*)sep;
        #pragma unroll
        for (int k = 0; k < 8; k++) v[k] = __ldg(&s4[lane + 32 * k]);
    } else {
        const float4* yr = (const float4*)(y + ((size_t)b * 512 + (s - lx - 2)) * DD);
        #pragma unroll
        for (int k = 0; k < 8; k++) {
            float4 a = __ldg(&yr[lane + 32 * k]), p = pys4[lane + 32 * k];
            v[k].x = a.x + p.x; v[k].y = a.y + p.y; v[k].z = a.z + p.z; v[k].w = a.w + p.w;
        }
    }
}

// ---------- FRONT: q0qhat -> scores -> stats, one persistent kernel ------------
__global__ void __launch_bounds__(256) k_front(
        const float* __restrict__ x, const float* __restrict__ y,
        const float* __restrict__ cls, const float* __restrict__ sep,
        const float* __restrict__ px, const float* __restrict__ py,
        const float* __restrict__ Wqkv, const float* __restrict__ bqkv,
        const int* __restrict__ x_len, const int* __restrict__ y_len) {
    extern __shared__ __align__(16) float dsm[];
    float* qh  = dsm;                    // 16384
    float* pxs = dsm + NH * DD;          // 1024
    float* pys = pxs + DD;               // 1024
    float* qbs = pys + DD;               // 16
    __shared__ __align__(16) float clss[DD];
    __shared__ float q0s[HDIM];
    __shared__ float sred[8];

    int blk = blockIdx.x;                // 0..127
    int t = threadIdx.x, w = t >> 5, lane = t & 31;

    // ---- P0: q0 + qhat. blk -> (h = blk>>3, qq = blk&7 covers 128 cols) ------
    {
        int h = blk >> 3, qq = blk & 7;
        for (int i = t; i < DD / 4; i += 256)
            ((float4*)clss)[i] = ((const float4*)cls)[i];
        __syncthreads();
        const float4* c4 = (const float4*)clss;
        for (int jr = 0; jr < 8; jr++) {
            int j = w * 8 + jr;
            const float4* Wr = (const float4*)(Wqkv + (size_t)(h * HDIM + j) * DD);
            float acc = 0.f;
            for (int i = lane; i < DD / 4; i += 32) {
                float4 wv = Wr[i], cv = c4[i];
                acc += wv.x * cv.x + wv.y * cv.y + wv.z * cv.z + wv.w * cv.w;
            }
            #pragma unroll
            for (int o = 16; o; o >>= 1) acc += __shfl_xor_sync(0xffffffffu, acc, o);
            if (lane == 0) q0s[j] = acc + bqkv[h * HDIM + j];
        }
        __syncthreads();
        if (t < 128) {
            int d = qq * 128 + t;
            float acc = 0.f;
            #pragma unroll 4
            for (int j = 0; j < HDIM; j++)
                acc += q0s[j] * Wqkv[(size_t)(DD + h * HDIM + j) * DD + d];
            g_qhat[h * DD + d] = acc;
        }
        if (qq == 0 && t == 0) {
            float s = 0.f;
            for (int j = 0; j < HDIM; j++) s += q0s[j] * bqkv[DD + h * HDIM + j];
            g_qb[h] = s;
        }
    }
    grid_sync();

    // ---- P1: scores. blk -> (sblk = blk&15, b = blk>>4) ----------------------
    {
        int sblk = blk & 15, b = blk >> 4;
        float4* qh4 = (float4*)qh;
        for (int i = t; i < NH * DD / 4; i += 256) qh4[i] = ((const float4*)g_qhat)[i];
        if (t < 256) { ((float4*)pxs)[t] = ((const float4*)px)[t]; ((float4*)pys)[t] = ((const float4*)py)[t]; }
        if (t < NH) qbs[t] = g_qb[t];
        __syncthreads();

        int lx = x_len[b], ly = y_len[b];
        int Sb = lx + ly + 3;
        const float4* pxs4 = (const float4*)pxs;
        const float4* pys4 = (const float4*)pys;

        for (int s = sblk * 16 + w * 2; s < Sb; s += 256) {
            bool two = (s + 1 < Sb);
            float4 v0[8], v1[8];
            fetch_pos(s, lx, ly, b, lane, x, y, cls, sep, pxs4, pys4, v0);
            if (two) fetch_pos(s + 1, lx, ly, b, lane, x, y, cls, sep, pxs4, pys4, v1);

            float acc0[NH], acc1[NH];
            #pragma unroll
            for (int h = 0; h < NH; h++) {
                float a0 = 0.f, a1 = 0.f;
                const float4* q4 = qh4 + h * 256;
                #pragma unroll
                for (int k = 0; k < 8; k++) {
                    float4 qv = q4[lane + 32 * k];
                    a0 += qv.x * v0[k].x + qv.y * v0[k].y + qv.z * v0[k].z + qv.w * v0[k].w;
                    if (two)
                        a1 += qv.x * v1[k].x + qv.y * v1[k].y + qv.z * v1[k].z + qv.w * v1[k].w;
                }
                acc0[h] = a0; acc1[h] = a1;
            }
            #pragma unroll
            for (int h = 0; h < NH; h++) {
                #pragma unroll
                for (int o = 16; o; o >>= 1) {
                    acc0[h] += __shfl_xor_sync(0xffffffffu, acc0[h], o);
                    acc1[h] += __shfl_xor_sync(0xffffffffu, acc1[h], o);
                }
            }
            if (lane == 0) {
                #pragma unroll
                for (int h = 0; h < NH; h++) {
                    float* sp = g_scores + ((size_t)b * NH + h) * SP + s;
                    sp[0] = (acc0[h] + qbs[h]) * 0.125f;
                    if (two) sp[1] = (acc1[h] + qbs[h]) * 0.125f;
                }
            }
        }
    }
    grid_sync();

    // ---- P2: softmax stats. bh = blk -----------------------------------------
    {
        int bh = blk;
        int b  = bh >> 4;
        int Sb = x_len[b] + y_len[b] + 3;
        const float* sc = g_scores + (size_t)bh * SP;

        float m = -1e30f;
        for (int s = t; s < Sb; s += 256) m = fmaxf(m, sc[s]);
        #pragma unroll
        for (int o = 16; o; o >>= 1) m = fmaxf(m, __shfl_xor_sync(0xffffffffu, m, o));
        if ((t & 31) == 0) sred[t >> 5] = m;
        __syncthreads();
        m = sred[0];
        #pragma unroll
        for (int i = 1; i < 8; i++) m = fmaxf(m, sred[i]);

        float sum = 0.f;
        for (int s = t; s < Sb; s += 256) sum += __expf(sc[s] - m);
        #pragma unroll
        for (int o = 16; o; o >>= 1) sum += __shfl_xor_sync(0xffffffffu, sum, o);
        __syncthreads();
        if ((t & 31) == 0) sred[t >> 5] = sum;
        __syncthreads();
        if (t == 0) {
            float ss = 0.f;
            #pragma unroll
            for (int i = 0; i < 8; i++) ss += sred[i];
            g_minv[bh * 2]     = m;
            g_minv[bh * 2 + 1] = 1.f / ss;
        }
    }
}

// ---------- ctx partials (R10, unchanged): grid (NC, 2, BB), block 256 ---------
#define ROWU 512
__global__ void __launch_bounds__(256) k_ctx(
        const float* __restrict__ x, const float* __restrict__ y,
        const float* __restrict__ cls, const float* __restrict__ sep,
        const float* __restrict__ px, const float* __restrict__ py,
        const int* __restrict__ x_len, const int* __restrict__ y_len) {
    int c  = blockIdx.x;
    int dq = blockIdx.y;
    int b  = blockIdx.z;
    int t  = threadIdx.x;
    int d2 = dq * 256 + t;
    int lx = x_len[b], ly = y_len[b];
    int Sb = lx + ly + 3;
    int cl = (Sb + NC - 1) / NC;
    int s0 = c * cl, s1 = min(s0 + cl, Sb);
    int n  = s1 - s0;

    if (n <= 0) {
        #pragma unroll
        for (int h = 0; h < NH; h++)
            ((ull*)(g_ctxp + (((size_t)b * NC + c) * NH + h) * DD))[d2] = 0ull;
        return;
    }

    __shared__ ull a2[NH][36];
    __shared__ float minv[NH * 2];
    if (t < NH * 2) minv[t] = g_minv[b * NH * 2 + t];
    __syncthreads();
    for (int i = t; i < n * NH; i += 256) {
        int h = i & 15, ss = i >> 4;
        float e = __expf(g_scores[((size_t)b * NH + h) * SP + s0 + ss] - minv[h * 2]) * minv[h * 2 + 1];
        a2[h][ss] = pack2same(e);
    }
    __syncthreads();

    ull acc[NH];
    #pragma unroll
    for (int h = 0; h < NH; h++) acc[h] = 0ull;

    if (s0 == 0) {
        ull cv = ((const ull*)cls)[d2];
        #pragma unroll
        for (int h = 0; h < NH; h++) FMA2(acc[h], a2[h][0], cv);
    }
    {
        int p0 = max(s0, 1), p1 = min(s1, lx + 1);
        if (p0 < p1) {
            ull pxv = ((const ull*)px)[d2];
            const ull* xp = (const ull*)x + ((size_t)b * 512 + (p0 - 1)) * ROWU + d2;
            int nn = p1 - p0, base = p0 - s0;
            int s = 0;
            for (; s + 2 <= nn; s += 2) {
                ull r0 = xp[(size_t)s * ROWU];
                ull r1 = xp[(size_t)(s + 1) * ROWU];
                ull v0, v1;
                ADD2(v0, r0, pxv);
                ADD2(v1, r1, pxv);
                int ss = base + s;
                #pragma unroll
                for (int h = 0; h < NH; h++) {
                    FMA2(acc[h], a2[h][ss], v0);
                    FMA2(acc[h], a2[h][ss + 1], v1);
                }
            }
            if (s < nn) {
                ull r0 = xp[(size_t)s * ROWU];
                ull v0;
                ADD2(v0, r0, pxv);
                int ss = base + s;
                #pragma unroll
                for (int h = 0; h < NH; h++) FMA2(acc[h], a2[h][ss], v0);
            }
        }
    }
    {
        int sA = lx + 1, sB = lx + ly + 2;
        bool hA = (sA >= s0 && sA < s1), hB = (sB >= s0 && sB < s1);
        if (hA || hB) {
            ull sv = ((const ull*)sep)[d2];
            if (hA) {
                #pragma unroll
                for (int h = 0; h < NH; h++) FMA2(acc[h], a2[h][sA - s0], sv);
            }
            if (hB) {
                #pragma unroll
                for (int h = 0; h < NH; h++) FMA2(acc[h], a2[h][sB - s0], sv);
            }
        }
    }
    {
        int p0 = max(s0, lx + 2), p1 = min(s1, lx + ly + 2);
        if (p0 < p1) {
            ull pyv = ((const ull*)py)[d2];
            const ull* yp = (const ull*)y + ((size_t)b * 512 + (p0 - lx - 2)) * ROWU + d2;
            int nn = p1 - p0, base = p0 - s0;
            int s = 0;
            for (; s + 2 <= nn; s += 2) {
                ull r0 = yp[(size_t)s * ROWU];
                ull r1 = yp[(size_t)(s + 1) * ROWU];
                ull v0, v1;
                ADD2(v0, r0, pyv);
                ADD2(v1, r1, pyv);
                int ss = base + s;
                #pragma unroll
                for (int h = 0; h < NH; h++) {
                    FMA2(acc[h], a2[h][ss], v0);
                    FMA2(acc[h], a2[h][ss + 1], v1);
                }
            }
            if (s < nn) {
                ull r0 = yp[(size_t)s * ROWU];
                ull v0;
                ADD2(v0, r0, pyv);
                int ss = base + s;
                #pragma unroll
                for (int h = 0; h < NH; h++) FMA2(acc[h], a2[h][ss], v0);
            }
        }
    }
    #pragma unroll
    for (int h = 0; h < NH; h++)
        ((ull*)(g_ctxp + (((size_t)b * NC + c) * NH + h) * DD))[d2] = acc[h];
}

// ---------- EPILOGUE: reduce -> Vproj -> Wo -> LN1+W1 -> W2 -> LN2 -------------
__global__ void __launch_bounds__(256) k_epi(
        const float* __restrict__ Wqkv, const float* __restrict__ bqkv,
        const float* __restrict__ Wo,   const float* __restrict__ bo,
        const float* __restrict__ W1,   const float* __restrict__ b1,
        const float* __restrict__ W2,   const float* __restrict__ b2,
        const float* __restrict__ ln1g, const float* __restrict__ ln1b,
        const float* __restrict__ ln2g, const float* __restrict__ ln2b,
        const float* __restrict__ cls,  float* __restrict__ outp) {
    __shared__ __align__(16) float xs[BB * 1024];     // 32KB
    __shared__ __align__(16) float gs[1024], bs2[1024];
    __shared__ float sred[8];
    __shared__ float smv[2];
    int blk = blockIdx.x, t = threadIdx.x, w = t >> 5, lane = t & 31;
    float4* xs4 = (float4*)xs;

    // ---- P0: ctx chunk reduce (32768 float4 over 32768 threads) --------------
    {
        int i4 = blk * 256 + t;
        int b  = i4 >> 12;                 // 4096 float4 per batch
        int j  = i4 & 4095;
        float4 s = {0.f, 0.f, 0.f, 0.f};
        #pragma unroll
        for (int c = 0; c < NC; c++) {
            float4 v = ((const float4*)(g_ctxp + ((size_t)b * NC + c) * (NH * DD)))[j];
            s.x += v.x; s.y += v.y; s.z += v.z; s.w += v.w;
        }
        ((float4*)(g_ctx + (size_t)b * (NH * DD)))[i4 & 4095 | 0] = s;  // j
        ((float4*)(g_ctx + (size_t)b * (NH * DD)))[j] = s;
    }
    grid_sync();

    // ---- P1: V projection (1024 rows, 8/block) --------------------------------
    {
        int e = blk * 8 + w;
        int h = (blk * 8) >> 6;
        for (int i = t; i < BB * DD / 4; i += 256) {
            int b = i >> 8, j4 = i & 255;
            xs4[i] = ((const float4*)(g_ctx + ((size_t)b * NH + h) * DD))[j4];
        }
        __syncthreads();
        const float4* Wr = (const float4*)(Wqkv + (size_t)(2 * DD + e) * DD);
        float acc[BB];
        #pragma unroll
        for (int b = 0; b < BB; b++) acc[b] = 0.f;
        for (int i = lane; i < DD / 4; i += 32) {
            float4 wv = Wr[i];
            #pragma unroll
            for (int b = 0; b < BB; b++) {
                float4 x4 = xs4[b * 256 + i];
                acc[b] += wv.x * x4.x + wv.y * x4.y + wv.z * x4.z + wv.w * x4.w;
            }
        }
        #pragma unroll
        for (int b = 0; b < BB; b++) {
            #pragma unroll
            for (int o = 16; o; o >>= 1)
                acc[b] += __shfl_xor_sync(0xffffffffu, acc[b], o);
        }
        if (lane == 0) {
            float be = bqkv[2 * DD + e];
            #pragma unroll
            for (int b = 0; b < BB; b++)
                g_oattn[(size_t)b * DD + e] = acc[b] + be;
        }
    }
    grid_sync();

    // ---- P2: Wo projection + cls residual -> g_ores ---------------------------
    {
        int e = blk * 8 + w;
        for (int i = t; i < BB * 256; i += 256)
            xs4[i] = ((const float4*)g_oattn)[i];
        __syncthreads();
        const float4* Wr = (const float4*)(Wo + (size_t)e * DD);
        float acc[BB];
        #pragma unroll
        for (int b = 0; b < BB; b++) acc[b] = 0.f;
        for (int i = lane; i < DD / 4; i += 32) {
            float4 wv = Wr[i];
            #pragma unroll
            for (int b = 0; b < BB; b++) {
                float4 x4 = xs4[b * 256 + i];
                acc[b] += wv.x * x4.x + wv.y * x4.y + wv.z * x4.z + wv.w * x4.w;
            }
        }
        #pragma unroll
        for (int b = 0; b < BB; b++) {
            #pragma unroll
            for (int o = 16; o; o >>= 1)
                acc[b] += __shfl_xor_sync(0xffffffffu, acc[b], o);
        }
        if (lane == 0) {
            float be = bo[e] + cls[e];
            #pragma unroll
            for (int b = 0; b < BB; b++)
                g_ores[(size_t)b * DD + e] = acc[b] + be;
        }
    }
    grid_sync();

    // ---- P3: LN1 (in smem) + W1 + relu (16 rows/block) -> g_f, g_h1 ----------
    {
        for (int i = t; i < BB * 256; i += 256)
            xs4[i] = ((const float4*)g_ores)[i];
        if (t < 256) { ((float4*)gs)[t] = ((const float4*)ln1g)[t]; ((float4*)bs2)[t] = ((const float4*)ln1b)[t]; }
        __syncthreads();
        float* row = xs + w * 1024;
        if (w < BB) {
            float s = 0.f;
            #pragma unroll
            for (int j = 0; j < 32; j++) s += row[lane + 32 * j];
            #pragma unroll
            for (int o = 16; o; o >>= 1) s += __shfl_xor_sync(0xffffffffu, s, o);
            float m = s * (1.f / 1024.f);
            float v = 0.f;
            #pragma unroll
            for (int j = 0; j < 32; j++) { float dd2 = row[lane + 32 * j] - m; v += dd2 * dd2; }
            #pragma unroll
            for (int o = 16; o; o >>= 1) v += __shfl_xor_sync(0xffffffffu, v, o);
            float r = rsqrtf(v * (1.f / 1024.f) + EPSL);
            #pragma unroll
            for (int j = 0; j < 32; j++) {
                int idx = lane + 32 * j;
                row[idx] = (row[idx] - m) * r * gs[idx] + bs2[idx];
            }
        }
        __syncthreads();
        if (blk == 0) {
            for (int i = t; i < BB * 256; i += 256)
                ((float4*)g_h1)[i] = xs4[i];
        }
        #pragma unroll
        for (int jr = 0; jr < 2; jr++) {
            int e = blk * 16 + w * 2 + jr;
            const float4* Wr = (const float4*)(W1 + (size_t)e * DD);
            float acc[BB];
            #pragma unroll
            for (int b = 0; b < BB; b++) acc[b] = 0.f;
            for (int i = lane; i < DD / 4; i += 32) {
                float4 wv = Wr[i];
                #pragma unroll
                for (int b = 0; b < BB; b++) {
                    float4 x4 = xs4[b * 256 + i];
                    acc[b] += wv.x * x4.x + wv.y * x4.y + wv.z * x4.z + wv.w * x4.w;
                }
            }
            #pragma unroll
            for (int b = 0; b < BB; b++) {
                #pragma unroll
                for (int o = 16; o; o >>= 1)
                    acc[b] += __shfl_xor_sync(0xffffffffu, acc[b], o);
            }
            if (lane == 0) {
                float be = b1[e];
                #pragma unroll
                for (int b = 0; b < BB; b++)
                    g_f[(size_t)b * FF + e] = fmaxf(acc[b] + be, 0.f);
            }
        }
    }
    grid_sync();

    // ---- P4: W2 (IN=2048, 2 chunks) + h1 residual -> g_f2 ---------------------
    {
        int e = blk * 8 + w;
        float acc[BB];
        #pragma unroll
        for (int b = 0; b < BB; b++) acc[b] = 0.f;
        for (int kc = 0; kc < 2; kc++) {
            for (int i = t; i < BB * 256; i += 256) {
                int b = i >> 8, j4 = i & 255;
                xs4[i] = ((const float4*)(g_f + (size_t)b * FF + kc * 1024))[j4];
            }
            __syncthreads();
            const float4* Wr = (const float4*)(W2 + (size_t)e * FF + kc * 1024);
            for (int i = lane; i < 256; i += 32) {
                float4 wv = Wr[i];
                #pragma unroll
                for (int b = 0; b < BB; b++) {
                    float4 x4 = xs4[b * 256 + i];
                    acc[b] += wv.x * x4.x + wv.y * x4.y + wv.z * x4.z + wv.w * x4.w;
                }
            }
            __syncthreads();
        }
        #pragma unroll
        for (int b = 0; b < BB; b++) {
            #pragma unroll
            for (int o = 16; o; o >>= 1)
                acc[b] += __shfl_xor_sync(0xffffffffu, acc[b], o);
        }
        if (lane == 0) {
            float be = b2[e];
            #pragma unroll
            for (int b = 0; b < BB; b++)
                g_f2[(size_t)b * DD + e] = acc[b] + be + g_h1[(size_t)b * DD + e];
        }
    }
    grid_sync();

    // ---- P5: LN2 -> out (blocks 0..7) -----------------------------------------
    if (blk < BB) {
        int b = blk;
        const float* row = g_f2 + (size_t)b * DD;
        float s = 0.f;
        for (int i = t; i < DD; i += 256) s += row[i];
        #pragma unroll
        for (int o = 16; o; o >>= 1) s += __shfl_xor_sync(0xffffffffu, s, o);
        if ((t & 31) == 0) sred[t >> 5] = s;
        __syncthreads();
        if (t == 0) {
            float m = 0.f;
            #pragma unroll
            for (int i = 0; i < 8; i++) m += sred[i];
            smv[0] = m * (1.f / DD);
        }
        __syncthreads();
        float m = smv[0];
        float v = 0.f;
        for (int i = t; i < DD; i += 256) { float dd2 = row[i] - m; v += dd2 * dd2; }
        #pragma unroll
        for (int o = 16; o; o >>= 1) v += __shfl_xor_sync(0xffffffffu, v, o);
        __syncthreads();
        if ((t & 31) == 0) sred[t >> 5] = v;
        __syncthreads();
        if (t == 0) {
            float vv = 0.f;
            #pragma unroll
            for (int i = 0; i < 8; i++) vv += sred[i];
            smv[1] = rsqrtf(vv * (1.f / DD) + EPSL);
        }
        __syncthreads();
        float r = smv[1];
        for (int i = t; i < DD; i += 256)
            outp[(size_t)b * DD + i] = (row[i] - m) * r * ln2g[i] + ln2b[i];
    }
}

extern "C" void kernel_launch(void* const* d_in, const int* in_sizes, int n_in,
                              void* d_out, int out_size) {
    const float* x     = (const float*)d_in[0];
    const float* y     = (const float*)d_in[1];
    const float* cls   = (const float*)d_in[2];
    const float* sep   = (const float*)d_in[3];
    const float* px    = (const float*)d_in[4];
    const float* py    = (const float*)d_in[5];
    const float* Wqkv  = (const float*)d_in[6];
    const float* bqkv  = (const float*)d_in[7];
    const float* Wo    = (const float*)d_in[8];
    const float* bo    = (const float*)d_in[9];
    const float* W1    = (const float*)d_in[10];
    const float* b1    = (const float*)d_in[11];
    const float* W2    = (const float*)d_in[12];
    const float* b2    = (const float*)d_in[13];
    const float* ln1g  = (const float*)d_in[14];
    const float* ln1b  = (const float*)d_in[15];
    const float* ln2g  = (const float*)d_in[16];
    const float* ln2b  = (const float*)d_in[17];
    const int*   x_len = (const int*)d_in[18];
    const int*   y_len = (const int*)d_in[19];
    float* outp = (float*)d_out;

    const int FRONT_SMEM = (NH * DD + 2 * DD + 16) * (int)sizeof(float);  // ~74KB
    cudaFuncSetAttribute(k_front, cudaFuncAttributeMaxDynamicSharedMemorySize, FRONT_SMEM);

    k_front<<<NB, 256, FRONT_SMEM>>>(x, y, cls, sep, px, py, Wqkv, bqkv, x_len, y_len);
    k_ctx<<<dim3(NC, 2, BB), 256>>>(x, y, cls, sep, px, py, x_len, y_len);
    k_epi<<<NB, 256>>>(Wqkv, bqkv, Wo, bo, W1, b1, W2, b2,
                       ln1g, ln1b, ln2g, ln2b, cls, outp);
}

// round 12
// speedup vs baseline: 1.0389x; 1.0389x over previous
#include <cuda_runtime.h>
#include <math.h>

#define DD   1024
#define NH   16
#define HDIM 64
#define FF   2048
#define BB   8
#define SS   1027
#define SP   1056
#define EPSL 1e-5f
#define NC   32
#define NB   128            // persistent epilogue block count (<= 148 SMs)

typedef unsigned long long ull;

__device__ __forceinline__ ull pack2same(float v) {
    unsigned u = __float_as_uint(v);
    return ((ull)u << 32) | u;
}
#define FMA2(d, a, b) asm("fma.rn.f32x2 %0, %1, %2, %0;" : "+l"(d) : "l"(a), "l"(b))
#define ADD2(d, a, b) asm("add.rn.f32x2 %0, %1, %2;" : "=l"(d) : "l"(a), "l"(b))

__device__ float g_scores[(size_t)BB * NH * SP];
__device__ float g_minv[BB * NH * 2];
__device__ float g_qhat[NH * DD];
__device__ float g_qb[NH];
__device__ float g_ctxp[(size_t)BB * NC * NH * DD];
__device__ float g_ctx[(size_t)BB * NH * DD];
__device__ float g_oattn[BB * DD];
__device__ float g_ores[BB * DD];
__device__ float g_h1[BB * DD];
__device__ float g_f[BB * FF];
__device__ float g_f2[BB * DD];

// ---------- grid barrier for the persistent epilogue ---------------------------
__device__ unsigned g_count;
__device__ volatile unsigned g_gen;

__device__ __forceinline__ void grid_sync() {
    __threadfence();
    __syncthreads();
    if (threadIdx.x == 0) {
        unsigned my = g_gen;
        if (atomicAdd(&g_count, 1u) == NB - 1) {
            g_count = 0;
            __threadfence();
            g_gen = my + 1;
        } else {
            while (g_gen == my) __nanosleep(64);
        }
    }
    __syncthreads();
    __threadfence();
}

// ---------- q0 + qhat: grid (NH, 4) --------------------------------------------
__global__ void k_q0qhat(const float* __restrict__ Wqkv, const float* __restrict__ bqkv,
                         const float* __restrict__ cls) {
    int h = blockIdx.x, q = blockIdx.y;
    int t = threadIdx.x;                 // 256
    int w = t >> 5, lane = t & 31;
    __shared__ __align__(16) float clss[DD];
    __shared__ float q0s[HDIM];

    for (int i = t; i < DD / 4; i += 256)
        ((float4*)clss)[i] = ((const float4*)cls)[i];
    __syncthreads();

    const float4* c4 = (const float4*)clss;
    for (int jr = 0; jr < 8; jr++) {
        int j = w * 8 + jr;
        const float4* Wr = (const float4*)(Wqkv + (size_t)(h * HDIM + j) * DD);
        float acc = 0.f;
        for (int i = lane; i < DD / 4; i += 32) {
            float4 wv = Wr[i], cv = c4[i];
            acc += wv.x * cv.x + wv.y * cv.y + wv.z * cv.z + wv.w * cv.w;
        }
        #pragma unroll
        for (int o = 16; o; o >>= 1) acc += __shfl_xor_sync(0xffffffffu, acc, o);
        if (lane == 0) q0s[j] = acc + bqkv[h * HDIM + j];
    }
    __syncthreads();

    int d = q * 256 + t;
    float acc = 0.f;
    #pragma unroll 4
    for (int j = 0; j < HDIM; j++)
        acc += q0s[j] * Wqkv[(size_t)(DD + h * HDIM + j) * DD + d];
    g_qhat[h * DD + d] = acc;
    if (q == 0 && t == 0) {
        float s = 0.f;
        for (int j = 0; j < HDIM; j++) s += q0s[j] * bqkv[DD + h * HDIM + j];
        g_qb[h] = s;
    }
}

// ---------- position fetch helper -----------------------------------------------
__device__ __forceinline__ void fetch_pos(
    int s, int lx, int ly, int b, int lane,
    const float* __restrict__ x, const float* __restrict__ y,
    const float* __restrict__ cls, const float* __restrict__ sep,
    const float4* __restrict__ pxs4, const float4* __restrict__ pys4,
    float4 v[8]) {
    if (s == 0) {
        const float4* c4 = (const float4*)cls;
        #pragma unroll
        for (int k = 0; k < 8; k++) v[k] = __ldg(&c4[lane + 32 * k]);
    } else if (s <= lx) {
        const float4* xr = (const float4*)(x + ((size_t)b * 512 + (s - 1)) * DD);
        #pragma unroll
        for (int k = 0; k < 8; k++) {
            float4 a = __ldg(&xr[lane + 32 * k]), p = pxs4[lane + 32 * k];
            v[k].x = a.x + p.x; v[k].y = a.y + p.y; v[k].z = a.z + p.z; v[k].w = a.w + p.w;
        }
    } else if (s == lx + 1 || s == lx + ly + 2) {
        const float4* s4 = (const float4*)sep;
        #pragma unroll
        for (int k = 0; k < 8; k++) v[k] = __ldg(&s4[lane + 32 * k]);
    } else {
        const float4* yr = (const float4*)(y + ((size_t)b * 512 + (s - lx - 2)) * DD);
        #pragma unroll
        for (int k = 0; k < 8; k++) {
            float4 a = __ldg(&yr[lane + 32 * k]), p = pys4[lane + 32 * k];
            v[k].x = a.x + p.x; v[k].y = a.y + p.y; v[k].z = a.z + p.z; v[k].w = a.w + p.w;
        }
    }
}

// ---------- scores: 2 positions/warp, scalar dots, grid (16, BB) -----------------
__global__ void k_scores(const float* __restrict__ x, const float* __restrict__ y,
                         const float* __restrict__ cls, const float* __restrict__ sep,
                         const float* __restrict__ px, const float* __restrict__ py,
                         const int* __restrict__ x_len, const int* __restrict__ y_len) {
    extern __shared__ __align__(16) float dsm[];
    float* qh  = dsm;                    // 16384
    float* pxs = dsm + NH * DD;          // 1024
    float* pys = pxs + DD;               // 1024
    float* qbs = pys + DD;               // 16
    int b = blockIdx.y;
    int t = threadIdx.x, w = t >> 5, lane = t & 31;

    float4* qh4 = (float4*)qh;
    for (int i = t; i < NH * DD / 4; i += 256) qh4[i] = ((const float4*)g_qhat)[i];
    if (t < 256) { ((float4*)pxs)[t] = ((const float4*)px)[t]; ((float4*)pys)[t] = ((const float4*)py)[t]; }
    if (t < NH) qbs[t] = g_qb[t];
    __syncthreads();

    int lx = x_len[b], ly = y_len[b];
    int Sb = lx + ly + 3;
    const float4* pxs4 = (const float4*)pxs;
    const float4* pys4 = (const float4*)pys;

    for (int s = blockIdx.x * 16 + w * 2; s < Sb; s += 256) {
        bool two = (s + 1 < Sb);
        float4 v0[8], v1[8];
        fetch_pos(s, lx, ly, b, lane, x, y, cls, sep, pxs4, pys4, v0);
        if (two) fetch_pos(s + 1, lx, ly, b, lane, x, y, cls, sep, pxs4, pys4, v1);

        float acc0[NH], acc1[NH];
        #pragma unroll
        for (int h = 0; h < NH; h++) {
            float a0 = 0.f, a1 = 0.f;
            const float4* q4 = qh4 + h * 256;
            #pragma unroll
            for (int k = 0; k < 8; k++) {
                float4 qv = q4[lane + 32 * k];
                a0 += qv.x * v0[k].x + qv.y * v0[k].y + qv.z * v0[k].z + qv.w * v0[k].w;
                if (two)
                    a1 += qv.x * v1[k].x + qv.y * v1[k].y + qv.z * v1[k].z + qv.w * v1[k].w;
            }
            acc0[h] = a0; acc1[h] = a1;
        }
        #pragma unroll
        for (int h = 0; h < NH; h++) {
            #pragma unroll
            for (int o = 16; o; o >>= 1) {
                acc0[h] += __shfl_xor_sync(0xffffffffu, acc0[h], o);
                acc1[h] += __shfl_xor_sync(0xffffffffu, acc1[h], o);
            }
        }
        if (lane == 0) {
            #pragma unroll
            for (int h = 0; h < NH; h++) {
                float* sp = g_scores + ((size_t)b * NH + h) * SP + s;
                sp[0] = (acc0[h] + qbs[h]) * 0.125f;
                if (two) sp[1] = (acc1[h] + qbs[h]) * 0.125f;
            }
        }
    }
}

// ---------- softmax stats --------------------------------------------------------
__global__ void k_stats(const int* __restrict__ x_len, const int* __restrict__ y_len) {
    int bh = blockIdx.x;
    int b  = bh >> 4;
    int Sb = x_len[b] + y_len[b] + 3;
    int t  = threadIdx.x;                // 256
    const float* sc = g_scores + (size_t)bh * SP;
    __shared__ float sred[8];

    float m = -1e30f;
    for (int s = t; s < Sb; s += 256) m = fmaxf(m, sc[s]);
    #pragma unroll
    for (int o = 16; o; o >>= 1) m = fmaxf(m, __shfl_xor_sync(0xffffffffu, m, o));
    if ((t & 31) == 0) sred[t >> 5] = m;
    __syncthreads();
    m = sred[0];
    #pragma unroll
    for (int i = 1; i < 8; i++) m = fmaxf(m, sred[i]);

    float sum = 0.f;
    for (int s = t; s < Sb; s += 256) sum += __expf(sc[s] - m);
    #pragma unroll
    for (int o = 16; o; o >>= 1) sum += __shfl_xor_sync(0xffffffffu, sum, o);
    __syncthreads();
    if ((t & 31) == 0) sred[t >> 5] = sum;
    __syncthreads();
    if (t == 0) {
        float ss = 0.f;
        #pragma unroll
        for (int i = 0; i < 8; i++) ss += sred[i];
        g_minv[bh * 2]     = m;
        g_minv[bh * 2 + 1] = 1.f / ss;
    }
}

// ---------- ctx partials: float2/thread + f32x2, grid (NC, 2, BB), block 256 ------
#define ROWU 512
__global__ void __launch_bounds__(256) k_ctx(
        const float* __restrict__ x, const float* __restrict__ y,
        const float* __restrict__ cls, const float* __restrict__ sep,
        const float* __restrict__ px, const float* __restrict__ py,
        const int* __restrict__ x_len, const int* __restrict__ y_len) {
    int c  = blockIdx.x;
    int dq = blockIdx.y;
    int b  = blockIdx.z;
    int t  = threadIdx.x;
    int d2 = dq * 256 + t;
    int lx = x_len[b], ly = y_len[b];
    int Sb = lx + ly + 3;
    int cl = (Sb + NC - 1) / NC;
    int s0 = c * cl, s1 = min(s0 + cl, Sb);
    int n  = s1 - s0;

    if (n <= 0) {
        #pragma unroll
        for (int h = 0; h < NH; h++)
            ((ull*)(g_ctxp + (((size_t)b * NC + c) * NH + h) * DD))[d2] = 0ull;
        return;
    }

    __shared__ ull a2[NH][36];
    __shared__ float minv[NH * 2];
    if (t < NH * 2) minv[t] = g_minv[b * NH * 2 + t];
    __syncthreads();
    for (int i = t; i < n * NH; i += 256) {
        int h = i & 15, ss = i >> 4;
        float e = __expf(g_scores[((size_t)b * NH + h) * SP + s0 + ss] - minv[h * 2]) * minv[h * 2 + 1];
        a2[h][ss] = pack2same(e);
    }
    __syncthreads();

    ull acc[NH];
    #pragma unroll
    for (int h = 0; h < NH; h++) acc[h] = 0ull;

    if (s0 == 0) {
        ull cv = ((const ull*)cls)[d2];
        #pragma unroll
        for (int h = 0; h < NH; h++) FMA2(acc[h], a2[h][0], cv);
    }
    {
        int p0 = max(s0, 1), p1 = min(s1, lx + 1);
        if (p0 < p1) {
            ull pxv = ((const ull*)px)[d2];
            const ull* xp = (const ull*)x + ((size_t)b * 512 + (p0 - 1)) * ROWU + d2;
            int nn = p1 - p0, base = p0 - s0;
            int s = 0;
            for (; s + 2 <= nn; s += 2) {
                ull r0 = xp[(size_t)s * ROWU];
                ull r1 = xp[(size_t)(s + 1) * ROWU];
                ull v0, v1;
                ADD2(v0, r0, pxv);
                ADD2(v1, r1, pxv);
                int ss = base + s;
                #pragma unroll
                for (int h = 0; h < NH; h++) {
                    FMA2(acc[h], a2[h][ss], v0);
                    FMA2(acc[h], a2[h][ss + 1], v1);
                }
            }
            if (s < nn) {
                ull r0 = xp[(size_t)s * ROWU];
                ull v0;
                ADD2(v0, r0, pxv);
                int ss = base + s;
                #pragma unroll
                for (int h = 0; h < NH; h++) FMA2(acc[h], a2[h][ss], v0);
            }
        }
    }
    {
        int sA = lx + 1, sB = lx + ly + 2;
        bool hA = (sA >= s0 && sA < s1), hB = (sB >= s0 && sB < s1);
        if (hA || hB) {
            ull sv = ((const ull*)sep)[d2];
            if (hA) {
                #pragma unroll
                for (int h = 0; h < NH; h++) FMA2(acc[h], a2[h][sA - s0], sv);
            }
            if (hB) {
                #pragma unroll
                for (int h = 0; h < NH; h++) FMA2(acc[h], a2[h][sB - s0], sv);
            }
        }
    }
    {
        int p0 = max(s0, lx + 2), p1 = min(s1, lx + ly + 2);
        if (p0 < p1) {
            ull pyv = ((const ull*)py)[d2];
            const ull* yp = (const ull*)y + ((size_t)b * 512 + (p0 - lx - 2)) * ROWU + d2;
            int nn = p1 - p0, base = p0 - s0;
            int s = 0;
            for (; s + 2 <= nn; s += 2) {
                ull r0 = yp[(size_t)s * ROWU];
                ull r1 = yp[(size_t)(s + 1) * ROWU];
                ull v0, v1;
                ADD2(v0, r0, pyv);
                ADD2(v1, r1, pyv);
                int ss = base + s;
                #pragma unroll
                for (int h = 0; h < NH; h++) {
                    FMA2(acc[h], a2[h][ss], v0);
                    FMA2(acc[h], a2[h][ss + 1], v1);
                }
            }
            if (s < nn) {
                ull r0 = yp[(size_t)s * ROWU];
                ull v0;
                ADD2(v0, r0, pyv);
                int ss = base + s;
                #pragma unroll
                for (int h = 0; h < NH; h++) FMA2(acc[h], a2[h][ss], v0);
            }
        }
    }
    #pragma unroll
    for (int h = 0; h < NH; h++)
        ((ull*)(g_ctxp + (((size_t)b * NC + c) * NH + h) * DD))[d2] = acc[h];
}

// ---------- EPILOGUE (validated in R11): reduce -> Vproj -> Wo -> LN1+W1 -> W2 -> LN2
__global__ void __launch_bounds__(256) k_epi(
        const float* __restrict__ Wqkv, const float* __restrict__ bqkv,
        const float* __restrict__ Wo,   const float* __restrict__ bo,
        const float* __restrict__ W1,   const float* __restrict__ b1,
        const float* __restrict__ W2,   const float* __restrict__ b2,
        const float* __restrict__ ln1g, const float* __restrict__ ln1b,
        const float* __restrict__ ln2g, const float* __restrict__ ln2b,
        const float* __restrict__ cls,  float* __restrict__ outp) {
    __shared__ __align__(16) float xs[BB * 1024];     // 32KB
    __shared__ __align__(16) float gs[1024], bs2[1024];
    __shared__ float sred[8];
    __shared__ float smv[2];
    int blk = blockIdx.x, t = threadIdx.x, w = t >> 5, lane = t & 31;
    float4* xs4 = (float4*)xs;

    // ---- P0: ctx chunk reduce ---------------------------------------------------
    {
        int i4 = blk * 256 + t;
        int b  = i4 >> 12;
        int j  = i4 & 4095;
        float4 s = {0.f, 0.f, 0.f, 0.f};
        #pragma unroll
        for (int c = 0; c < NC; c++) {
            float4 v = ((const float4*)(g_ctxp + ((size_t)b * NC + c) * (NH * DD)))[j];
            s.x += v.x; s.y += v.y; s.z += v.z; s.w += v.w;
        }
        ((float4*)(g_ctx + (size_t)b * (NH * DD)))[j] = s;
    }
    grid_sync();

    // ---- P1: V projection ---------------------------------------------------------
    {
        int e = blk * 8 + w;
        int h = (blk * 8) >> 6;
        for (int i = t; i < BB * DD / 4; i += 256) {
            int b = i >> 8, j4 = i & 255;
            xs4[i] = ((const float4*)(g_ctx + ((size_t)b * NH + h) * DD))[j4];
        }
        __syncthreads();
        const float4* Wr = (const float4*)(Wqkv + (size_t)(2 * DD + e) * DD);
        float acc[BB];
        #pragma unroll
        for (int b = 0; b < BB; b++) acc[b] = 0.f;
        for (int i = lane; i < DD / 4; i += 32) {
            float4 wv = Wr[i];
            #pragma unroll
            for (int b = 0; b < BB; b++) {
                float4 x4 = xs4[b * 256 + i];
                acc[b] += wv.x * x4.x + wv.y * x4.y + wv.z * x4.z + wv.w * x4.w;
            }
        }
        #pragma unroll
        for (int b = 0; b < BB; b++) {
            #pragma unroll
            for (int o = 16; o; o >>= 1)
                acc[b] += __shfl_xor_sync(0xffffffffu, acc[b], o);
        }
        if (lane == 0) {
            float be = bqkv[2 * DD + e];
            #pragma unroll
            for (int b = 0; b < BB; b++)
                g_oattn[(size_t)b * DD + e] = acc[b] + be;
        }
    }
    grid_sync();

    // ---- P2: Wo projection + cls residual ------------------------------------------
    {
        int e = blk * 8 + w;
        for (int i = t; i < BB * 256; i += 256)
            xs4[i] = ((const float4*)g_oattn)[i];
        __syncthreads();
        const float4* Wr = (const float4*)(Wo + (size_t)e * DD);
        float acc[BB];
        #pragma unroll
        for (int b = 0; b < BB; b++) acc[b] = 0.f;
        for (int i = lane; i < DD / 4; i += 32) {
            float4 wv = Wr[i];
            #pragma unroll
            for (int b = 0; b < BB; b++) {
                float4 x4 = xs4[b * 256 + i];
                acc[b] += wv.x * x4.x + wv.y * x4.y + wv.z * x4.z + wv.w * x4.w;
            }
        }
        #pragma unroll
        for (int b = 0; b < BB; b++) {
            #pragma unroll
            for (int o = 16; o; o >>= 1)
                acc[b] += __shfl_xor_sync(0xffffffffu, acc[b], o);
        }
        if (lane == 0) {
            float be = bo[e] + cls[e];
            #pragma unroll
            for (int b = 0; b < BB; b++)
                g_ores[(size_t)b * DD + e] = acc[b] + be;
        }
    }
    grid_sync();

    // ---- P3: LN1 (in smem) + W1 + relu ----------------------------------------------
    {
        for (int i = t; i < BB * 256; i += 256)
            xs4[i] = ((const float4*)g_ores)[i];
        if (t < 256) { ((float4*)gs)[t] = ((const float4*)ln1g)[t]; ((float4*)bs2)[t] = ((const float4*)ln1b)[t]; }
        __syncthreads();
        float* row = xs + w * 1024;
        {
            float s = 0.f;
            #pragma unroll
            for (int j = 0; j < 32; j++) s += row[lane + 32 * j];
            #pragma unroll
            for (int o = 16; o; o >>= 1) s += __shfl_xor_sync(0xffffffffu, s, o);
            float m = s * (1.f / 1024.f);
            float v = 0.f;
            #pragma unroll
            for (int j = 0; j < 32; j++) { float dd2 = row[lane + 32 * j] - m; v += dd2 * dd2; }
            #pragma unroll
            for (int o = 16; o; o >>= 1) v += __shfl_xor_sync(0xffffffffu, v, o);
            float r = rsqrtf(v * (1.f / 1024.f) + EPSL);
            #pragma unroll
            for (int j = 0; j < 32; j++) {
                int idx = lane + 32 * j;
                row[idx] = (row[idx] - m) * r * gs[idx] + bs2[idx];
            }
        }
        __syncthreads();
        if (blk == 0) {
            for (int i = t; i < BB * 256; i += 256)
                ((float4*)g_h1)[i] = xs4[i];
        }
        #pragma unroll
        for (int jr = 0; jr < 2; jr++) {
            int e = blk * 16 + w * 2 + jr;
            const float4* Wr = (const float4*)(W1 + (size_t)e * DD);
            float acc[BB];
            #pragma unroll
            for (int b = 0; b < BB; b++) acc[b] = 0.f;
            for (int i = lane; i < DD / 4; i += 32) {
                float4 wv = Wr[i];
                #pragma unroll
                for (int b = 0; b < BB; b++) {
                    float4 x4 = xs4[b * 256 + i];
                    acc[b] += wv.x * x4.x + wv.y * x4.y + wv.z * x4.z + wv.w * x4.w;
                }
            }
            #pragma unroll
            for (int b = 0; b < BB; b++) {
                #pragma unroll
                for (int o = 16; o; o >>= 1)
                    acc[b] += __shfl_xor_sync(0xffffffffu, acc[b], o);
            }
            if (lane == 0) {
                float be = b1[e];
                #pragma unroll
                for (int b = 0; b < BB; b++)
                    g_f[(size_t)b * FF + e] = fmaxf(acc[b] + be, 0.f);
            }
        }
    }
    grid_sync();

    // ---- P4: W2 (IN=2048, 2 chunks) + h1 residual --------------------------------------
    {
        int e = blk * 8 + w;
        float acc[BB];
        #pragma unroll
        for (int b = 0; b < BB; b++) acc[b] = 0.f;
        for (int kc = 0; kc < 2; kc++) {
            for (int i = t; i < BB * 256; i += 256) {
                int b = i >> 8, j4 = i & 255;
                xs4[i] = ((const float4*)(g_f + (size_t)b * FF + kc * 1024))[j4];
            }
            __syncthreads();
            const float4* Wr = (const float4*)(W2 + (size_t)e * FF + kc * 1024);
            for (int i = lane; i < 256; i += 32) {
                float4 wv = Wr[i];
                #pragma unroll
                for (int b = 0; b < BB; b++) {
                    float4 x4 = xs4[b * 256 + i];
                    acc[b] += wv.x * x4.x + wv.y * x4.y + wv.z * x4.z + wv.w * x4.w;
                }
            }
            __syncthreads();
        }
        #pragma unroll
        for (int b = 0; b < BB; b++) {
            #pragma unroll
            for (int o = 16; o; o >>= 1)
                acc[b] += __shfl_xor_sync(0xffffffffu, acc[b], o);
        }
        if (lane == 0) {
            float be = b2[e];
            #pragma unroll
            for (int b = 0; b < BB; b++)
                g_f2[(size_t)b * DD + e] = acc[b] + be + g_h1[(size_t)b * DD + e];
        }
    }
    grid_sync();

    // ---- P5: LN2 -> out (blocks 0..7) ---------------------------------------------------
    if (blk < BB) {
        int b = blk;
        const float* row = g_f2 + (size_t)b * DD;
        float s = 0.f;
        for (int i = t; i < DD; i += 256) s += row[i];
        #pragma unroll
        for (int o = 16; o; o >>= 1) s += __shfl_xor_sync(0xffffffffu, s, o);
        if ((t & 31) == 0) sred[t >> 5] = s;
        __syncthreads();
        if (t == 0) {
            float m = 0.f;
            #pragma unroll
            for (int i = 0; i < 8; i++) m += sred[i];
            smv[0] = m * (1.f / DD);
        }
        __syncthreads();
        float m = smv[0];
        float v = 0.f;
        for (int i = t; i < DD; i += 256) { float dd2 = row[i] - m; v += dd2 * dd2; }
        #pragma unroll
        for (int o = 16; o; o >>= 1) v += __shfl_xor_sync(0xffffffffu, v, o);
        __syncthreads();
        if ((t & 31) == 0) sred[t >> 5] = v;
        __syncthreads();
        if (t == 0) {
            float vv = 0.f;
            #pragma unroll
            for (int i = 0; i < 8; i++) vv += sred[i];
            smv[1] = rsqrtf(vv * (1.f / DD) + EPSL);
        }
        __syncthreads();
        float r = smv[1];
        for (int i = t; i < DD; i += 256)
            outp[(size_t)b * DD + i] = (row[i] - m) * r * ln2g[i] + ln2b[i];
    }
}

extern "C" void kernel_launch(void* const* d_in, const int* in_sizes, int n_in,
                              void* d_out, int out_size) {
    const float* x     = (const float*)d_in[0];
    const float* y     = (const float*)d_in[1];
    const float* cls   = (const float*)d_in[2];
    const float* sep   = (const float*)d_in[3];
    const float* px    = (const float*)d_in[4];
    const float* py    = (const float*)d_in[5];
    const float* Wqkv  = (const float*)d_in[6];
    const float* bqkv  = (const float*)d_in[7];
    const float* Wo    = (const float*)d_in[8];
    const float* bo    = (const float*)d_in[9];
    const float* W1    = (const float*)d_in[10];
    const float* b1    = (const float*)d_in[11];
    const float* W2    = (const float*)d_in[12];
    const float* b2    = (const float*)d_in[13];
    const float* ln1g  = (const float*)d_in[14];
    const float* ln1b  = (const float*)d_in[15];
    const float* ln2g  = (const float*)d_in[16];
    const float* ln2b  = (const float*)d_in[17];
    const int*   x_len = (const int*)d_in[18];
    const int*   y_len = (const int*)d_in[19];
    float* outp = (float*)d_out;

    const int SCORES_SMEM = (NH * DD + 2 * DD + 16) * (int)sizeof(float);  // ~74KB
    cudaFuncSetAttribute(k_scores, cudaFuncAttributeMaxDynamicSharedMemorySize, SCORES_SMEM);

    k_q0qhat<<<dim3(NH, 4), 256>>>(Wqkv, bqkv, cls);
    k_scores<<<dim3(16, BB), 256, SCORES_SMEM>>>(x, y, cls, sep, px, py, x_len, y_len);
    k_stats<<<BB * NH, 256>>>(x_len, y_len);
    k_ctx<<<dim3(NC, 2, BB), 256>>>(x, y, cls, sep, px, py, x_len, y_len);
    k_epi<<<NB, 256>>>(Wqkv, bqkv, Wo, bo, W1, b1, W2, b2,
                       ln1g, ln1b, ln2g, ln2b, cls, outp);
}

// round 13
// speedup vs baseline: 1.0858x; 1.0452x over previous
#include <cuda_runtime.h>
#include <math.h>

#define DD   1024
#define NH   16
#define HDIM 64
#define FF   2048
#define BB   8
#define SS   1027
#define SP   1056
#define EPSL 1e-5f
#define NC   32

typedef unsigned long long ull;

__device__ __forceinline__ ull pack2same(float v) {
    unsigned u = __float_as_uint(v);
    return ((ull)u << 32) | u;
}
#define FMA2(d, a, b) asm("fma.rn.f32x2 %0, %1, %2, %0;" : "+l"(d) : "l"(a), "l"(b))
#define ADD2(d, a, b) asm("add.rn.f32x2 %0, %1, %2;" : "=l"(d) : "l"(a), "l"(b))

__device__ float g_scores[(size_t)BB * NH * SP];     // [b][h][s]
__device__ float g_cstat[BB * NC * NH * 2];          // per-chunk (m, sum)
__device__ float g_qhat[NH * DD];
__device__ float g_qb[NH];
__device__ float g_ctxp[(size_t)BB * NC * NH * DD];  // unnormalized chunk ctx
__device__ float g_ctx[(size_t)BB * NH * DD];
__device__ float g_oattn[BB * DD];
__device__ float g_ores[BB * DD];
__device__ float g_h1[BB * DD];
__device__ float g_f[BB * FF];
__device__ float g_f2[BB * DD];

// ---------- q0 + qhat: grid (NH, 4) --------------------------------------------
__global__ void k_q0qhat(const float* __restrict__ Wqkv, const float* __restrict__ bqkv,
                         const float* __restrict__ cls) {
    int h = blockIdx.x, q = blockIdx.y;
    int t = threadIdx.x;                 // 256
    int w = t >> 5, lane = t & 31;
    __shared__ __align__(16) float clss[DD];
    __shared__ float q0s[HDIM];

    for (int i = t; i < DD / 4; i += 256)
        ((float4*)clss)[i] = ((const float4*)cls)[i];
    __syncthreads();

    const float4* c4 = (const float4*)clss;
    for (int jr = 0; jr < 8; jr++) {
        int j = w * 8 + jr;
        const float4* Wr = (const float4*)(Wqkv + (size_t)(h * HDIM + j) * DD);
        float acc = 0.f;
        for (int i = lane; i < DD / 4; i += 32) {
            float4 wv = Wr[i], cv = c4[i];
            acc += wv.x * cv.x + wv.y * cv.y + wv.z * cv.z + wv.w * cv.w;
        }
        #pragma unroll
        for (int o = 16; o; o >>= 1) acc += __shfl_xor_sync(0xffffffffu, acc, o);
        if (lane == 0) q0s[j] = acc + bqkv[h * HDIM + j];
    }
    __syncthreads();

    int d = q * 256 + t;
    float acc = 0.f;
    #pragma unroll 4
    for (int j = 0; j < HDIM; j++)
        acc += q0s[j] * Wqkv[(size_t)(DD + h * HDIM + j) * DD + d];
    g_qhat[h * DD + d] = acc;
    if (q == 0 && t == 0) {
        float s = 0.f;
        for (int j = 0; j < HDIM; j++) s += q0s[j] * bqkv[DD + h * HDIM + j];
        g_qb[h] = s;
    }
}

// ---------- position fetch helper -----------------------------------------------
__device__ __forceinline__ void fetch_pos(
    int s, int lx, int ly, int b, int lane,
    const float* __restrict__ x, const float* __restrict__ y,
    const float* __restrict__ cls, const float* __restrict__ sep,
    const float4* __restrict__ pxs4, const float4* __restrict__ pys4,
    float4 v[8]) {
    if (s == 0) {
        const float4* c4 = (const float4*)cls;
        #pragma unroll
        for (int k = 0; k < 8; k++) v[k] = __ldg(&c4[lane + 32 * k]);
    } else if (s <= lx) {
        const float4* xr = (const float4*)(x + ((size_t)b * 512 + (s - 1)) * DD);
        #pragma unroll
        for (int k = 0; k < 8; k++) {
            float4 a = __ldg(&xr[lane + 32 * k]), p = pxs4[lane + 32 * k];
            v[k].x = a.x + p.x; v[k].y = a.y + p.y; v[k].z = a.z + p.z; v[k].w = a.w + p.w;
        }
    } else if (s == lx + 1 || s == lx + ly + 2) {
        const float4* s4 = (const float4*)sep;
        #pragma unroll
        for (int k = 0; k < 8; k++) v[k] = __ldg(&s4[lane + 32 * k]);
    } else {
        const float4* yr = (const float4*)(y + ((size_t)b * 512 + (s - lx - 2)) * DD);
        #pragma unroll
        for (int k = 0; k < 8; k++) {
            float4 a = __ldg(&yr[lane + 32 * k]), p = pys4[lane + 32 * k];
            v[k].x = a.x + p.x; v[k].y = a.y + p.y; v[k].z = a.z + p.z; v[k].w = a.w + p.w;
        }
    }
}

// ---------- scores: 2 positions/warp, grid (19, BB) ------------------------------
__global__ void k_scores(const float* __restrict__ x, const float* __restrict__ y,
                         const float* __restrict__ cls, const float* __restrict__ sep,
                         const float* __restrict__ px, const float* __restrict__ py,
                         const int* __restrict__ x_len, const int* __restrict__ y_len) {
    extern __shared__ __align__(16) float dsm[];
    float* qh  = dsm;                    // 16384
    float* pxs = dsm + NH * DD;          // 1024
    float* pys = pxs + DD;               // 1024
    float* qbs = pys + DD;               // 16
    int b = blockIdx.y;
    int t = threadIdx.x, w = t >> 5, lane = t & 31;

    float4* qh4 = (float4*)qh;
    for (int i = t; i < NH * DD / 4; i += 256) qh4[i] = ((const float4*)g_qhat)[i];
    if (t < 256) { ((float4*)pxs)[t] = ((const float4*)px)[t]; ((float4*)pys)[t] = ((const float4*)py)[t]; }
    if (t < NH) qbs[t] = g_qb[t];
    __syncthreads();

    int lx = x_len[b], ly = y_len[b];
    int Sb = lx + ly + 3;
    const float4* pxs4 = (const float4*)pxs;
    const float4* pys4 = (const float4*)pys;
    int stride = gridDim.x * 16;

    for (int s = blockIdx.x * 16 + w * 2; s < Sb; s += stride) {
        bool two = (s + 1 < Sb);
        float4 v0[8], v1[8];
        fetch_pos(s, lx, ly, b, lane, x, y, cls, sep, pxs4, pys4, v0);
        if (two) fetch_pos(s + 1, lx, ly, b, lane, x, y, cls, sep, pxs4, pys4, v1);

        float acc0[NH], acc1[NH];
        #pragma unroll
        for (int h = 0; h < NH; h++) {
            float a0 = 0.f, a1 = 0.f;
            const float4* q4 = qh4 + h * 256;
            #pragma unroll
            for (int k = 0; k < 8; k++) {
                float4 qv = q4[lane + 32 * k];
                a0 += qv.x * v0[k].x + qv.y * v0[k].y + qv.z * v0[k].z + qv.w * v0[k].w;
                if (two)
                    a1 += qv.x * v1[k].x + qv.y * v1[k].y + qv.z * v1[k].z + qv.w * v1[k].w;
            }
            acc0[h] = a0; acc1[h] = a1;
        }
        #pragma unroll
        for (int h = 0; h < NH; h++) {
            #pragma unroll
            for (int o = 16; o; o >>= 1) {
                acc0[h] += __shfl_xor_sync(0xffffffffu, acc0[h], o);
                acc1[h] += __shfl_xor_sync(0xffffffffu, acc1[h], o);
            }
        }
        if (lane == 0) {
            #pragma unroll
            for (int h = 0; h < NH; h++) {
                float* sp = g_scores + ((size_t)b * NH + h) * SP + s;
                sp[0] = (acc0[h] + qbs[h]) * 0.125f;
                if (two) sp[1] = (acc1[h] + qbs[h]) * 0.125f;
            }
        }
    }
}

// ---------- ctx partials with LOCAL softmax stats (flash-style) -------------------
// grid (NC, 2, BB), block 256. Writes unnormalized ctx + per-chunk (m, sum).
#define ROWU 512
__global__ void __launch_bounds__(256) k_ctx(
        const float* __restrict__ x, const float* __restrict__ y,
        const float* __restrict__ cls, const float* __restrict__ sep,
        const float* __restrict__ px, const float* __restrict__ py,
        const int* __restrict__ x_len, const int* __restrict__ y_len) {
    int c  = blockIdx.x;
    int dq = blockIdx.y;
    int b  = blockIdx.z;
    int t  = threadIdx.x;
    int d2 = dq * 256 + t;
    int lx = x_len[b], ly = y_len[b];
    int Sb = lx + ly + 3;
    int cl = (Sb + NC - 1) / NC;
    int s0 = c * cl, s1 = min(s0 + cl, Sb);
    int n  = s1 - s0;

    if (n <= 0) {
        #pragma unroll
        for (int h = 0; h < NH; h++)
            ((ull*)(g_ctxp + (((size_t)b * NC + c) * NH + h) * DD))[d2] = 0ull;
        if (dq == 0 && t < NH) {
            g_cstat[((b * NC + c) * NH + t) * 2]     = -1e30f;
            g_cstat[((b * NC + c) * NH + t) * 2 + 1] = 0.f;
        }
        return;
    }

    __shared__ ull a2[NH][36];
    __shared__ float lm[NH];
    // local per-head max + sum over this chunk (16 threads, serial over <=33)
    if (t < NH) {
        int h = t;
        const float* sc = g_scores + ((size_t)b * NH + h) * SP + s0;
        float m = -1e30f;
        for (int ss = 0; ss < n; ss++) m = fmaxf(m, sc[ss]);
        float sum = 0.f;
        for (int ss = 0; ss < n; ss++) sum += __expf(sc[ss] - m);
        lm[h] = m;
        if (dq == 0) {
            g_cstat[((b * NC + c) * NH + h) * 2]     = m;
            g_cstat[((b * NC + c) * NH + h) * 2 + 1] = sum;
        }
    }
    __syncthreads();
    for (int i = t; i < n * NH; i += 256) {
        int h = i & 15, ss = i >> 4;
        float e = __expf(g_scores[((size_t)b * NH + h) * SP + s0 + ss] - lm[h]);
        a2[h][ss] = pack2same(e);
    }
    __syncthreads();

    ull acc[NH];
    #pragma unroll
    for (int h = 0; h < NH; h++) acc[h] = 0ull;

    if (s0 == 0) {
        ull cv = ((const ull*)cls)[d2];
        #pragma unroll
        for (int h = 0; h < NH; h++) FMA2(acc[h], a2[h][0], cv);
    }
    {
        int p0 = max(s0, 1), p1 = min(s1, lx + 1);
        if (p0 < p1) {
            ull pxv = ((const ull*)px)[d2];
            const ull* xp = (const ull*)x + ((size_t)b * 512 + (p0 - 1)) * ROWU + d2;
            int nn = p1 - p0, base = p0 - s0;
            int s = 0;
            for (; s + 2 <= nn; s += 2) {
                ull r0 = xp[(size_t)s * ROWU];
                ull r1 = xp[(size_t)(s + 1) * ROWU];
                ull v0, v1;
                ADD2(v0, r0, pxv);
                ADD2(v1, r1, pxv);
                int ss = base + s;
                #pragma unroll
                for (int h = 0; h < NH; h++) {
                    FMA2(acc[h], a2[h][ss], v0);
                    FMA2(acc[h], a2[h][ss + 1], v1);
                }
            }
            if (s < nn) {
                ull r0 = xp[(size_t)s * ROWU];
                ull v0;
                ADD2(v0, r0, pxv);
                int ss = base + s;
                #pragma unroll
                for (int h = 0; h < NH; h++) FMA2(acc[h], a2[h][ss], v0);
            }
        }
    }
    {
        int sA = lx + 1, sB = lx + ly + 2;
        bool hA = (sA >= s0 && sA < s1), hB = (sB >= s0 && sB < s1);
        if (hA || hB) {
            ull sv = ((const ull*)sep)[d2];
            if (hA) {
                #pragma unroll
                for (int h = 0; h < NH; h++) FMA2(acc[h], a2[h][sA - s0], sv);
            }
            if (hB) {
                #pragma unroll
                for (int h = 0; h < NH; h++) FMA2(acc[h], a2[h][sB - s0], sv);
            }
        }
    }
    {
        int p0 = max(s0, lx + 2), p1 = min(s1, lx + ly + 2);
        if (p0 < p1) {
            ull pyv = ((const ull*)py)[d2];
            const ull* yp = (const ull*)y + ((size_t)b * 512 + (p0 - lx - 2)) * ROWU + d2;
            int nn = p1 - p0, base = p0 - s0;
            int s = 0;
            for (; s + 2 <= nn; s += 2) {
                ull r0 = yp[(size_t)s * ROWU];
                ull r1 = yp[(size_t)(s + 1) * ROWU];
                ull v0, v1;
                ADD2(v0, r0, pyv);
                ADD2(v1, r1, pyv);
                int ss = base + s;
                #pragma unroll
                for (int h = 0; h < NH; h++) {
                    FMA2(acc[h], a2[h][ss], v0);
                    FMA2(acc[h], a2[h][ss + 1], v1);
                }
            }
            if (s < nn) {
                ull r0 = yp[(size_t)s * ROWU];
                ull v0;
                ADD2(v0, r0, pyv);
                int ss = base + s;
                #pragma unroll
                for (int h = 0; h < NH; h++) FMA2(acc[h], a2[h][ss], v0);
            }
        }
    }
    #pragma unroll
    for (int h = 0; h < NH; h++)
        ((ull*)(g_ctxp + (((size_t)b * NC + c) * NH + h) * DD))[d2] = acc[h];
}

// ---------- combine chunks (flash rescale): grid (BB, 16), block 256 --------------
__global__ void k_combine() {
    int b = blockIdx.x;
    int q = blockIdx.y;            // 0..15
    int t = threadIdx.x;           // 256
    __shared__ float wsc[NC][NH];  // per-(chunk,head) final weight
    __shared__ float Ms[NH];

    if (t < NH) {
        int h = t;
        float M = -1e30f;
        for (int c = 0; c < NC; c++)
            M = fmaxf(M, g_cstat[((b * NC + c) * NH + h) * 2]);
        Ms[h] = M;
        float den = 0.f;
        for (int c = 0; c < NC; c++)
            den += g_cstat[((b * NC + c) * NH + h) * 2 + 1] *
                   __expf(g_cstat[((b * NC + c) * NH + h) * 2] - M);
        wsc[0][h] = 1.f / den;     // temporary stash of 1/den in row 0
    }
    __syncthreads();
    // expand weights: w[c][h] = exp(m_ch - M_h) / den_h
    // (do in reverse order so row 0's stash is consumed before overwrite)
    if (t < 256) {
        float invden[2];
        // each thread handles 2 (c,h) pairs: indices t and t+256 over NC*NH=512
        #pragma unroll
        for (int r = 0; r < 2; r++) {
            int idx = t + r * 256;
            int c = idx >> 4, h = idx & 15;
            float inv = wsc[0][h];                 // 1/den stash (still valid: see below)
            invden[r] = inv * __expf(g_cstat[((b * NC + c) * NH + h) * 2] - Ms[h]);
        }
        __syncthreads();
        #pragma unroll
        for (int r = 0; r < 2; r++) {
            int idx = t + r * 256;
            int c = idx >> 4, h = idx & 15;
            wsc[c][h] = invden[r];
        }
    }
    __syncthreads();

    int j = q * 256 + t;           // float4 index over NH*DD/4 = 4096
    int h = j >> 8;                // DD/4 = 256 float4 per head
    float4 s = {0.f, 0.f, 0.f, 0.f};
    #pragma unroll
    for (int c = 0; c < NC; c++) {
        float4 v = ((const float4*)(g_ctxp + ((size_t)b * NC + c) * (NH * DD)))[j];
        float f = wsc[c][h];
        s.x += v.x * f; s.y += v.y * f; s.z += v.z * f; s.w += v.w * f;
    }
    ((float4*)(g_ctx + (size_t)b * (NH * DD)))[j] = s;
}

// ---------- V projection ------------------------------------------------------------
__global__ void k_gemvV(const float* __restrict__ Wqkv, const float* __restrict__ bqkv) {
    __shared__ __align__(16) float xs[BB * DD];
    int t = threadIdx.x;           // 256
    int w = t >> 5, lane = t & 31;
    int e = blockIdx.x * 8 + w;
    int h = (blockIdx.x * 8) >> 6;

    float4* xs4 = (float4*)xs;
    for (int i = t; i < BB * DD / 4; i += 256) {
        int b = i >> 8, j4 = i & 255;
        xs4[i] = ((const float4*)(g_ctx + ((size_t)b * NH + h) * DD))[j4];
    }
    __syncthreads();

    const float4* Wr = (const float4*)(Wqkv + (size_t)(2 * DD + e) * DD);
    float acc[BB];
    #pragma unroll
    for (int b = 0; b < BB; b++) acc[b] = 0.f;
    for (int i = lane; i < DD / 4; i += 32) {
        float4 wv = Wr[i];
        #pragma unroll
        for (int b = 0; b < BB; b++) {
            float4 x4 = xs4[b * 256 + i];
            acc[b] += wv.x * x4.x + wv.y * x4.y + wv.z * x4.z + wv.w * x4.w;
        }
    }
    #pragma unroll
    for (int b = 0; b < BB; b++) {
        #pragma unroll
        for (int o = 16; o; o >>= 1)
            acc[b] += __shfl_xor_sync(0xffffffffu, acc[b], o);
    }
    if (lane == 0) {
        float be = bqkv[2 * DD + e];
        #pragma unroll
        for (int b = 0; b < BB; b++)
            g_oattn[(size_t)b * DD + e] = acc[b] + be;
    }
}

// ---------- batch-shared GEMV, optional fused input-LN --------------------------------
__global__ void k_gemv8(const float* __restrict__ W, const float* __restrict__ xin,
                        const float* __restrict__ bias, const float* __restrict__ residE,
                        const float* __restrict__ residB, float* __restrict__ out,
                        int IN, int OUT, int doRelu,
                        int doLN, const float* __restrict__ lng, const float* __restrict__ lnb,
                        float* __restrict__ h1out) {
    __shared__ __align__(16) float xs[BB * 1024];
    __shared__ __align__(16) float gs[1024], bs[1024];
    int t = threadIdx.x;           // 256
    int w = t >> 5, lane = t & 31;
    int e = blockIdx.x * 8 + w;

    float acc[BB];
    #pragma unroll
    for (int b = 0; b < BB; b++) acc[b] = 0.f;

    float4* xs4 = (float4*)xs;
    int nchunk = IN >> 10;
    for (int kc = 0; kc < nchunk; kc++) {
        for (int i = t; i < BB * 256; i += 256) {
            int b = i >> 8, j4 = i & 255;
            xs4[i] = ((const float4*)(xin + (size_t)b * IN + kc * 1024))[j4];
        }
        if (doLN) {
            if (t < 256) { ((float4*)gs)[t] = ((const float4*)lng)[t]; ((float4*)bs)[t] = ((const float4*)lnb)[t]; }
            __syncthreads();
            float* row = xs + w * 1024;
            float s = 0.f;
            #pragma unroll
            for (int j = 0; j < 32; j++) s += row[lane + 32 * j];
            #pragma unroll
            for (int o = 16; o; o >>= 1) s += __shfl_xor_sync(0xffffffffu, s, o);
            float m = s * (1.f / 1024.f);
            float v = 0.f;
            #pragma unroll
            for (int j = 0; j < 32; j++) { float dd2 = row[lane + 32 * j] - m; v += dd2 * dd2; }
            #pragma unroll
            for (int o = 16; o; o >>= 1) v += __shfl_xor_sync(0xffffffffu, v, o);
            float r = rsqrtf(v * (1.f / 1024.f) + EPSL);
            #pragma unroll
            for (int j = 0; j < 32; j++) {
                int idx = lane + 32 * j;
                row[idx] = (row[idx] - m) * r * gs[idx] + bs[idx];
            }
            __syncthreads();
            if (h1out && blockIdx.x == 0) {
                for (int i = t; i < BB * 256; i += 256)
                    ((float4*)h1out)[i] = xs4[i];
            }
        } else {
            __syncthreads();
        }
        const float4* Wr = (const float4*)(W + (size_t)e * IN + kc * 1024);
        for (int i = lane; i < 256; i += 32) {
            float4 wv = Wr[i];
            #pragma unroll
            for (int b = 0; b < BB; b++) {
                float4 x4 = xs4[b * 256 + i];
                acc[b] += wv.x * x4.x + wv.y * x4.y + wv.z * x4.z + wv.w * x4.w;
            }
        }
        __syncthreads();
    }
    #pragma unroll
    for (int b = 0; b < BB; b++) {
        #pragma unroll
        for (int o = 16; o; o >>= 1)
            acc[b] += __shfl_xor_sync(0xffffffffu, acc[b], o);
    }
    if (lane == 0) {
        float be = (bias ? bias[e] : 0.f) + (residE ? residE[e] : 0.f);
        #pragma unroll
        for (int b = 0; b < BB; b++) {
            float v = acc[b] + be;
            if (residB) v += residB[(size_t)b * OUT + e];
            if (doRelu) v = fmaxf(v, 0.f);
            out[(size_t)b * OUT + e] = v;
        }
    }
}

// ---------- LayerNorm ------------------------------------------------------------------
__global__ void k_ln(const float* __restrict__ in, const float* __restrict__ gamma,
                     const float* __restrict__ beta, float* __restrict__ out) {
    int b = blockIdx.x, t = threadIdx.x;  // 256
    const float* row = in + (size_t)b * DD;
    __shared__ float sred[8];
    __shared__ float smv[2];

    float s = 0.f;
    for (int i = t; i < DD; i += 256) s += row[i];
    #pragma unroll
    for (int o = 16; o; o >>= 1) s += __shfl_xor_sync(0xffffffffu, s, o);
    if ((t & 31) == 0) sred[t >> 5] = s;
    __syncthreads();
    if (t == 0) {
        float m = 0.f;
        #pragma unroll
        for (int i = 0; i < 8; i++) m += sred[i];
        smv[0] = m * (1.f / DD);
    }
    __syncthreads();
    float m = smv[0];

    float v = 0.f;
    for (int i = t; i < DD; i += 256) { float dd2 = row[i] - m; v += dd2 * dd2; }
    #pragma unroll
    for (int o = 16; o; o >>= 1) v += __shfl_xor_sync(0xffffffffu, v, o);
    __syncthreads();
    if ((t & 31) == 0) sred[t >> 5] = v;
    __syncthreads();
    if (t == 0) {
        float vv = 0.f;
        #pragma unroll
        for (int i = 0; i < 8; i++) vv += sred[i];
        smv[1] = rsqrtf(vv * (1.f / DD) + EPSL);
    }
    __syncthreads();
    float r = smv[1];
    for (int i = t; i < DD; i += 256)
        out[(size_t)b * DD + i] = (row[i] - m) * r * gamma[i] + beta[i];
}

extern "C" void kernel_launch(void* const* d_in, const int* in_sizes, int n_in,
                              void* d_out, int out_size) {
    const float* x     = (const float*)d_in[0];
    const float* y     = (const float*)d_in[1];
    const float* cls   = (const float*)d_in[2];
    const float* sep   = (const float*)d_in[3];
    const float* px    = (const float*)d_in[4];
    const float* py    = (const float*)d_in[5];
    const float* Wqkv  = (const float*)d_in[6];
    const float* bqkv  = (const float*)d_in[7];
    const float* Wo    = (const float*)d_in[8];
    const float* bo    = (const float*)d_in[9];
    const float* W1    = (const float*)d_in[10];
    const float* b1    = (const float*)d_in[11];
    const float* W2    = (const float*)d_in[12];
    const float* b2    = (const float*)d_in[13];
    const float* ln1g  = (const float*)d_in[14];
    const float* ln1b  = (const float*)d_in[15];
    const float* ln2g  = (const float*)d_in[16];
    const float* ln2b  = (const float*)d_in[17];
    const int*   x_len = (const int*)d_in[18];
    const int*   y_len = (const int*)d_in[19];
    float* outp = (float*)d_out;

    float *p_oattn, *p_ores, *p_h1, *p_f, *p_f2;
    cudaGetSymbolAddress((void**)&p_oattn, g_oattn);
    cudaGetSymbolAddress((void**)&p_ores,  g_ores);
    cudaGetSymbolAddress((void**)&p_h1,    g_h1);
    cudaGetSymbolAddress((void**)&p_f,     g_f);
    cudaGetSymbolAddress((void**)&p_f2,    g_f2);

    const int SCORES_SMEM = (NH * DD + 2 * DD + 16) * (int)sizeof(float);  // ~74KB
    cudaFuncSetAttribute(k_scores, cudaFuncAttributeMaxDynamicSharedMemorySize, SCORES_SMEM);

    k_q0qhat<<<dim3(NH, 4), 256>>>(Wqkv, bqkv, cls);
    k_scores<<<dim3(19, BB), 256, SCORES_SMEM>>>(x, y, cls, sep, px, py, x_len, y_len);
    k_ctx<<<dim3(NC, 2, BB), 256>>>(x, y, cls, sep, px, py, x_len, y_len);
    k_combine<<<dim3(BB, 16), 256>>>();
    k_gemvV<<<DD / 8, 256>>>(Wqkv, bqkv);
    k_gemv8<<<DD / 8, 256>>>(Wo, p_oattn, bo, cls, nullptr, p_ores, DD, DD, 0,
                             0, nullptr, nullptr, nullptr);
    k_gemv8<<<FF / 8, 256>>>(W1, p_ores, b1, nullptr, nullptr, p_f, DD, FF, 1,
                             1, ln1g, ln1b, p_h1);
    k_gemv8<<<DD / 8, 256>>>(W2, p_f, b2, nullptr, p_h1, p_f2, FF, DD, 0,
                             0, nullptr, nullptr, nullptr);
    k_ln<<<BB, 256>>>(p_f2, ln2g, ln2b, outp);
}